// round 7
// baseline (speedup 1.0000x reference)
#include <cuda_runtime.h>
#include <math.h>

// SpectralEMA.  state_t = a*|state_{t-1}|*unit(x_t) + (1-rho)*x_t
//             = x_t * z_t / w_t,  z_t = a*m_{t-1} + omr*w_t,  m_t = |z_t|
// Real a (theta=0): m_t = rho*m_{t-1} + omr*w_t  -> affine scan; segments
// compose: m_out = rho^L * m_in + C_seg.
//
// Fused single kernel, register-capped (__launch_bounds__(256,6) keeps the
// hot scan at 6 blocks/SM; combine-path spills are confined to the cold
// finisher). Segment g=0 seeds the recurrence with m0=|init| so its C
// already equals rho^L*m0 + C0 -- no init reads in the combine. The last
// block of each (b,f-tile) column (threadfence+atomic) combines the G
// coefficients and reconstructs the output from x[S-1] read straight from
// the inputs.

#define G   16
#define UNR 4
#define MAX_BF   (32 * 4096)
#define MAX_COLS (MAX_BF / 512)

__device__ float        g_C[G * MAX_BF];
__device__ unsigned int g_cnt[MAX_COLS];   // zero-init; finisher resets

__device__ __forceinline__ float sigmoidf_(float x) {
    return 1.0f / (1.0f + expf(-x));
}

// |v| via single MUFU.RSQ
__device__ __forceinline__ float mag_(float vr, float vi) {
    float v2 = fmaxf(fmaf(vr, vr, vi * vi), 1e-37f);
    return v2 * rsqrtf(v2);
}

// ---------------- Fused kernel ----------------
__global__ __launch_bounds__(256, 6)
void fused_kernel(const float* __restrict__ fr, const float* __restrict__ fi,
                  const float* __restrict__ ir, const float* __restrict__ ii,
                  const float* __restrict__ rho_logit,
                  const float* __restrict__ theta_raw,
                  float2* __restrict__ out, int S, int F, int L)
{
    int F2 = F >> 1;
    int f2 = blockIdx.x * blockDim.x + threadIdx.x;
    int b  = blockIdx.y;
    int g  = blockIdx.z;

    float2 rl  = __ldg((const float2*)rho_logit + f2);
    float rho0 = sigmoidf_(rl.x), rho1 = sigmoidf_(rl.y);
    float om0  = 1.0f - rho0,     om1  = 1.0f - rho1;

    // Segment 0 seeds with m0=|init| -> its C becomes rho^L*m0 + C0.
    float C0 = 0.0f, C1 = 0.0f;
    if (g == 0) {
        size_t bfh = (size_t)b * (size_t)F2 + (size_t)f2;
        float2 s0 = __ldg((const float2*)ir + bfh);
        float2 s1 = __ldg((const float2*)ii + bfh);
        C0 = mag_(s0.x, s1.x);
        C1 = mag_(s0.y, s1.y);
    }

    size_t base = ((size_t)b * (size_t)S + (size_t)g * (size_t)L) * (size_t)F
                + (size_t)(f2 << 1);
    const float2* pr  = (const float2*)(fr + base);
    const float2* pim = (const float2*)(fi + base);
    size_t st = (size_t)F2;              // float2 stride per step

    int nch = L / UNR;
    float2 cr[UNR], ci[UNR];
#pragma unroll
    for (int k = 0; k < UNR; ++k) {
        cr[k] = __ldcs(pr  + (size_t)k * st);
        ci[k] = __ldcs(pim + (size_t)k * st);
    }
    pr  += (size_t)UNR * st;
    pim += (size_t)UNR * st;

#pragma unroll 1
    for (int j = 0; j < nch; ++j) {
        float2 nr[UNR], ni[UNR];
        if (j + 1 < nch) {
#pragma unroll
            for (int k = 0; k < UNR; ++k) {
                nr[k] = __ldcs(pr  + (size_t)k * st);
                ni[k] = __ldcs(pim + (size_t)k * st);
            }
            pr  += (size_t)UNR * st;
            pim += (size_t)UNR * st;
        }
#pragma unroll
        for (int k = 0; k < UNR; ++k) {
            float wa = mag_(cr[k].x, ci[k].x);
            float wb = mag_(cr[k].y, ci[k].y);
            C0 = fmaf(rho0, C0, om0 * wa);
            C1 = fmaf(rho1, C1, om1 * wb);
        }
#pragma unroll
        for (int k = 0; k < UNR; ++k) { cr[k] = nr[k]; ci[k] = ni[k]; }
    }

    size_t bf0 = (size_t)b * (size_t)F + (size_t)(f2 << 1);
    *(float2*)(g_C + (size_t)g * MAX_BF + bf0) = make_float2(C0, C1);

    // ---- arrive: last block of this column combines ----
    __threadfence();          // publish g_C (device scope)
    __syncthreads();
    __shared__ unsigned int s_last;
    int col = b * gridDim.x + blockIdx.x;
    if (threadIdx.x == 0) {
        unsigned int old = atomicAdd(&g_cnt[col], 1u);
        s_last = (old == (unsigned int)(G - 1)) ? 1u : 0u;
    }
    __syncthreads();
    if (!s_last) return;

    __threadfence();          // acquire other segments' g_C stores

    float2 tw = __ldg((const float2*)theta_raw + f2);

    if (tw.x == 0.0f && tw.y == 0.0f) {
        float D0 = __powf(rho0, (float)L);
        float D1 = __powf(rho1, (float)L);
        // m starts as segment-0's C (init already folded in)
        float2 cv = *(const float2*)(g_C + bf0);
        float m0 = cv.x, m1 = cv.y;
#pragma unroll
        for (int q = 1; q < G; ++q) {
            cv = *(const float2*)(g_C + (size_t)q * MAX_BF + bf0);
            m0 = fmaf(D0, m0, cv.x);
            m1 = fmaf(D1, m1, cv.y);
        }
        // x[S-1] straight from inputs
        size_t last = ((size_t)b * (size_t)S + (size_t)(S - 1)) * (size_t)F
                    + (size_t)(f2 << 1);
        float2 lr = *(const float2*)(fr + last);
        float2 li = *(const float2*)(fi + last);
        float w20 = fmaxf(fmaf(lr.x, lr.x, li.x * li.x), 1e-37f);
        float w21 = fmaxf(fmaf(lr.y, lr.y, li.y * li.y), 1e-37f);
        float sc0 = m0 * rsqrtf(w20);
        float sc1 = m1 * rsqrtf(w21);
        out[bf0]     = make_float2(lr.x * sc0, li.x * sc0);
        out[bf0 + 1] = make_float2(lr.y * sc1, li.y * sc1);
    } else {
        // general complex-a path (not taken for this dataset): full rescan
#pragma unroll 1
        for (int q = 0; q < 2; ++q) {
            int f = (f2 << 1) + q;
            float rho = (q == 0) ? rho0 : rho1;
            float th  = 3.14159265358979323846f * tanhf(q == 0 ? tw.x : tw.y);
            float ss, sc;
            sincosf(th, &ss, &sc);
            float ar = rho * sc, ai = rho * ss, omr = 1.0f - rho;
            size_t bfq = (size_t)b * (size_t)F + (size_t)f;
            float m = mag_(__ldg(ir + bfq), __ldg(ii + bfq));
            const float* p  = fr + (size_t)b * (size_t)S * (size_t)F + f;
            const float* pi = fi + (size_t)b * (size_t)S * (size_t)F + f;
            float zr = 0.f, zi = 0.f, rinv = 1.f, lxr = 0.f, lxi = 0.f;
            for (int s = 0; s < S; ++s) {
                float xr = __ldg(p), xi = __ldg(pi);
                p += F; pi += F;
                float x2 = fmaxf(fmaf(xr, xr, xi * xi), 1e-37f);
                float rv = rsqrtf(x2);
                float w  = x2 * rv;
                zr = fmaf(ar, m, omr * w);
                zi = ai * m;
                m = mag_(zr, zi);
                rinv = rv; lxr = xr; lxi = xi;
            }
            out[bfq] = make_float2((zr * lxr - zi * lxi) * rinv,
                                   fmaf(zr, lxi, zi * lxr) * rinv);
        }
    }

    // reset counter for the next graph replay (all arrivals already in)
    if (threadIdx.x == 0) g_cnt[col] = 0u;
}

// ---------------- Monolithic fallback (unexpected shapes) ----------------
__global__ __launch_bounds__(256)
void mono_kernel(const float* __restrict__ fr, const float* __restrict__ fi,
                 const float* __restrict__ ir, const float* __restrict__ ii,
                 const float* __restrict__ rho_logit,
                 const float* __restrict__ theta_raw,
                 float2* __restrict__ out, int S, int F)
{
    int f = blockIdx.x * blockDim.x + threadIdx.x;
    if (f >= F) return;
    int b = blockIdx.y;
    size_t bf = (size_t)b * (size_t)F + (size_t)f;

    float rho = sigmoidf_(rho_logit[f]);
    float th  = 3.14159265358979323846f * tanhf(theta_raw[f]);
    float ss, sc;
    sincosf(th, &ss, &sc);
    float ar = rho * sc, ai = rho * ss, omr = 1.0f - rho;

    float m = mag_(ir[bf], ii[bf]);

    const float* pr  = fr + (size_t)b * (size_t)S * (size_t)F + f;
    const float* pim = fi + (size_t)b * (size_t)S * (size_t)F + f;
    float zr = 0.f, zi = 0.f, rinv = 1.f, lxr = 0.f, lxi = 0.f;
    for (int s = 0; s < S; ++s) {
        float xr = __ldcs(pr), xi = __ldcs(pim);
        pr += F; pim += F;
        float x2 = fmaxf(fmaf(xr, xr, xi * xi), 1e-37f);
        float rv = rsqrtf(x2);
        float w  = x2 * rv;
        zr = fmaf(ar, m, omr * w);
        zi = ai * m;
        m = mag_(zr, zi);
        rinv = rv; lxr = xr; lxi = xi;
    }
    out[bf] = make_float2((zr * lxr - zi * lxi) * rinv,
                          fmaf(zr, lxi, zi * lxr) * rinv);
}

extern "C" void kernel_launch(void* const* d_in, const int* in_sizes, int n_in,
                              void* d_out, int out_size)
{
    const float* fr = (const float*)d_in[0];
    const float* fi = (const float*)d_in[1];
    const float* ir = (const float*)d_in[2];
    const float* ii = (const float*)d_in[3];
    const float* rl = (const float*)d_in[4];
    const float* tr = (const float*)d_in[5];

    int F  = in_sizes[4];
    int BF = in_sizes[2];
    int B  = BF / F;
    int S  = in_sizes[0] / BF;

    dim3 block(256);

    bool fast = (BF <= MAX_BF) && (F % 512 == 0) && (S % (G * UNR) == 0);
    if (fast) {
        int L  = S / G;
        int F2 = F / 2;
        dim3 grid(F2 / 256, B, G);
        fused_kernel<<<grid, block>>>(fr, fi, ir, ii, rl, tr,
                                      (float2*)d_out, S, F, L);
    } else {
        dim3 grid((F + 255) / 256, B);
        mono_kernel<<<grid, block>>>(fr, fi, ir, ii, rl, tr,
                                     (float2*)d_out, S, F);
    }
}

// round 8
// speedup vs baseline: 1.3833x; 1.3833x over previous
#include <cuda_runtime.h>
#include <math.h>

// SpectralEMA.  state_t = a*|state_{t-1}|*unit(x_t) + (1-rho)*x_t
//             = x_t * z_t / w_t,  z_t = a*m_{t-1} + omr*w_t,  m_t = |z_t|
// Real a (theta=0): m_t = rho*m_{t-1} + omr*w_t  -> affine scan; segments
// compose: m_out = rho^L * m_in + C_seg.
// Phase 1 (proven-optimal shape: float2 = 2 feat/thread, UNR=4, G=16,
//   4096 blocks, 40 regs, ~6.9 TB/s): per-segment coefficient C.
//   Segment 0 seeds with m0=|init| so its C already folds the init state.
//   Segment G-1 stores x[S-1] for the reconstruction.
// Phase 2 (tiny): combine G coefficients per chain, D=rho^L via integer
//   pow-by-squaring (no MUFU chain), reconstruct output from x[S-1].

#define G   16
#define UNR 4
#define MAX_BF (32 * 4096)

__device__ float  g_C[G * MAX_BF];
__device__ float2 g_lx[MAX_BF];   // x at s = S-1 per chain

__device__ __forceinline__ float sigmoidf_(float x) {
    return 1.0f / (1.0f + expf(-x));
}

// |v| via single MUFU.RSQ
__device__ __forceinline__ float mag_(float vr, float vi) {
    float v2 = fmaxf(fmaf(vr, vr, vi * vi), 1e-37f);
    return v2 * rsqrtf(v2);
}

// x^e, integer e >= 0, by squaring (no MUFU)
__device__ __forceinline__ float powi_(float x, int e) {
    float r = 1.0f;
    while (e) {
        if (e & 1) r *= x;
        x *= x;
        e >>= 1;
    }
    return r;
}

// ---------------- Phase 1: per-segment affine coefficient C ----------------
__global__ __launch_bounds__(256)
void phase1_kernel(const float* __restrict__ fr, const float* __restrict__ fi,
                   const float* __restrict__ ir, const float* __restrict__ ii,
                   const float* __restrict__ rho_logit,
                   int S, int F, int L)
{
    int F2 = F >> 1;
    int f2 = blockIdx.x * blockDim.x + threadIdx.x;
    if (f2 >= F2) return;
    int b = blockIdx.y;
    int g = blockIdx.z;

    float2 rl  = __ldg((const float2*)rho_logit + f2);
    float rho0 = sigmoidf_(rl.x), rho1 = sigmoidf_(rl.y);
    float om0  = 1.0f - rho0,     om1  = 1.0f - rho1;

    // Segment 0 seeds with m0=|init| -> its C becomes rho^L*m0 + C0.
    float C0 = 0.0f, C1 = 0.0f;
    if (g == 0) {
        size_t bfh = (size_t)b * (size_t)F2 + (size_t)f2;
        float2 s0 = __ldg((const float2*)ir + bfh);
        float2 s1 = __ldg((const float2*)ii + bfh);
        C0 = mag_(s0.x, s1.x);
        C1 = mag_(s0.y, s1.y);
    }

    size_t base = ((size_t)b * (size_t)S + (size_t)g * (size_t)L) * (size_t)F
                + (size_t)(f2 << 1);
    const float2* pr  = (const float2*)(fr + base);
    const float2* pim = (const float2*)(fi + base);
    size_t st = (size_t)F2;              // float2 stride per step

    float2 lxr = make_float2(0.f, 0.f), lxi = make_float2(0.f, 0.f);

    int nch = L / UNR;
    float2 cr[UNR], ci[UNR];
#pragma unroll
    for (int k = 0; k < UNR; ++k) {
        cr[k] = __ldcs(pr  + (size_t)k * st);
        ci[k] = __ldcs(pim + (size_t)k * st);
    }
    pr  += (size_t)UNR * st;
    pim += (size_t)UNR * st;

#pragma unroll 1
    for (int j = 0; j < nch; ++j) {
        float2 nr[UNR], ni[UNR];
        if (j + 1 < nch) {
#pragma unroll
            for (int k = 0; k < UNR; ++k) {
                nr[k] = __ldcs(pr  + (size_t)k * st);
                ni[k] = __ldcs(pim + (size_t)k * st);
            }
            pr  += (size_t)UNR * st;
            pim += (size_t)UNR * st;
        }
#pragma unroll
        for (int k = 0; k < UNR; ++k) {
            float wa = mag_(cr[k].x, ci[k].x);
            float wb = mag_(cr[k].y, ci[k].y);
            C0 = fmaf(rho0, C0, om0 * wa);
            C1 = fmaf(rho1, C1, om1 * wb);
            lxr = cr[k]; lxi = ci[k];
        }
#pragma unroll
        for (int k = 0; k < UNR; ++k) { cr[k] = nr[k]; ci[k] = ni[k]; }
    }

    size_t bf0 = (size_t)b * (size_t)F + (size_t)(f2 << 1);
    *(float2*)(g_C + (size_t)g * MAX_BF + bf0) = make_float2(C0, C1);
    if (g == G - 1) {
        g_lx[bf0]     = make_float2(lxr.x, lxi.x);
        g_lx[bf0 + 1] = make_float2(lxr.y, lxi.y);
    }
}

// ---------------- Phase 2: combine segments, write output ----------------
__global__ __launch_bounds__(256)
void phase2_kernel(const float* __restrict__ fr, const float* __restrict__ fi,
                   const float* __restrict__ ir, const float* __restrict__ ii,
                   const float* __restrict__ rho_logit,
                   const float* __restrict__ theta_raw,
                   float2* __restrict__ out, int S, int F, int L)
{
    int f = blockIdx.x * blockDim.x + threadIdx.x;
    if (f >= F) return;
    int b = blockIdx.y;
    size_t bf = (size_t)b * (size_t)F + (size_t)f;

    float thw = __ldg(theta_raw + f);
    float rho = sigmoidf_(__ldg(rho_logit + f));

    if (thw == 0.0f) {
        // 16 independent coalesced loads (max MLP), short FMA chain after
        float c[G];
#pragma unroll
        for (int g = 0; g < G; ++g)
            c[g] = __ldg(g_C + (size_t)g * MAX_BF + bf);
        float2 lx = g_lx[bf];

        float D = powi_(rho, L);   // 5 FMULs for L=32, no MUFU
        float m = c[0];            // init already folded into segment 0
#pragma unroll
        for (int g = 1; g < G; ++g)
            m = fmaf(D, m, c[g]);
        // m == z_last (real, >= 0).  out = x_last * m / |x_last|
        float w2 = fmaxf(fmaf(lx.x, lx.x, lx.y * lx.y), 1e-37f);
        float s  = m * rsqrtf(w2);
        out[bf] = make_float2(lx.x * s, lx.y * s);
    } else {
        // general complex-a path (not taken for this dataset): full rescan
        float th = 3.14159265358979323846f * tanhf(thw);
        float ss, sc;
        sincosf(th, &ss, &sc);
        float ar = rho * sc, ai = rho * ss, omr = 1.0f - rho;
        float m = mag_(__ldg(ir + bf), __ldg(ii + bf));
        const float* p  = fr + (size_t)b * (size_t)S * (size_t)F + f;
        const float* pi = fi + (size_t)b * (size_t)S * (size_t)F + f;
        float zr = 0.f, zi = 0.f, rinv = 1.f, lr = 0.f, li = 0.f;
        for (int s = 0; s < S; ++s) {
            float xr = __ldg(p), xi = __ldg(pi);
            p += F; pi += F;
            float x2 = fmaxf(fmaf(xr, xr, xi * xi), 1e-37f);
            float rv = rsqrtf(x2);
            float w  = x2 * rv;
            zr = fmaf(ar, m, omr * w);
            zi = ai * m;
            m = mag_(zr, zi);
            rinv = rv; lr = xr; li = xi;
        }
        out[bf] = make_float2((zr * lr - zi * li) * rinv,
                              fmaf(zr, li, zi * lr) * rinv);
    }
}

// ---------------- Monolithic fallback (unexpected shapes) ----------------
__global__ __launch_bounds__(256)
void mono_kernel(const float* __restrict__ fr, const float* __restrict__ fi,
                 const float* __restrict__ ir, const float* __restrict__ ii,
                 const float* __restrict__ rho_logit,
                 const float* __restrict__ theta_raw,
                 float2* __restrict__ out, int S, int F)
{
    int f = blockIdx.x * blockDim.x + threadIdx.x;
    if (f >= F) return;
    int b = blockIdx.y;
    size_t bf = (size_t)b * (size_t)F + (size_t)f;

    float rho = sigmoidf_(rho_logit[f]);
    float th  = 3.14159265358979323846f * tanhf(theta_raw[f]);
    float ss, sc;
    sincosf(th, &ss, &sc);
    float ar = rho * sc, ai = rho * ss, omr = 1.0f - rho;

    float m = mag_(ir[bf], ii[bf]);

    const float* pr  = fr + (size_t)b * (size_t)S * (size_t)F + f;
    const float* pim = fi + (size_t)b * (size_t)S * (size_t)F + f;
    float zr = 0.f, zi = 0.f, rinv = 1.f, lxr = 0.f, lxi = 0.f;
    for (int s = 0; s < S; ++s) {
        float xr = __ldcs(pr), xi = __ldcs(pim);
        pr += F; pim += F;
        float x2 = fmaxf(fmaf(xr, xr, xi * xi), 1e-37f);
        float rv = rsqrtf(x2);
        float w  = x2 * rv;
        zr = fmaf(ar, m, omr * w);
        zi = ai * m;
        m = mag_(zr, zi);
        rinv = rv; lxr = xr; lxi = xi;
    }
    out[bf] = make_float2((zr * lxr - zi * lxi) * rinv,
                          fmaf(zr, lxi, zi * lxr) * rinv);
}

extern "C" void kernel_launch(void* const* d_in, const int* in_sizes, int n_in,
                              void* d_out, int out_size)
{
    const float* fr = (const float*)d_in[0];
    const float* fi = (const float*)d_in[1];
    const float* ir = (const float*)d_in[2];
    const float* ii = (const float*)d_in[3];
    const float* rl = (const float*)d_in[4];
    const float* tr = (const float*)d_in[5];

    int F  = in_sizes[4];
    int BF = in_sizes[2];
    int B  = BF / F;
    int S  = in_sizes[0] / BF;

    dim3 block(256);

    bool fast = (BF <= MAX_BF) && (F % 512 == 0) && (S % (G * UNR) == 0);
    if (fast) {
        int L  = S / G;
        int F2 = F / 2;
        dim3 grid1(F2 / 256, B, G);
        phase1_kernel<<<grid1, block>>>(fr, fi, ir, ii, rl, S, F, L);
        dim3 grid2((F + 255) / 256, B);
        phase2_kernel<<<grid2, block>>>(fr, fi, ir, ii, rl, tr,
                                        (float2*)d_out, S, F, L);
    } else {
        dim3 grid((F + 255) / 256, B);
        mono_kernel<<<grid, block>>>(fr, fi, ir, ii, rl, tr,
                                     (float2*)d_out, S, F);
    }
}

// round 9
// speedup vs baseline: 1.3839x; 1.0004x over previous
#include <cuda_runtime.h>
#include <math.h>

// SpectralEMA.  state_t = a*|state_{t-1}|*unit(x_t) + (1-rho)*x_t
//             = x_t * z_t / w_t,  z_t = a*m_{t-1} + omr*w_t,  m_t = |z_t|
// Real a (theta=0): m_t = rho*m_{t-1} + omr*w_t  -> affine scan; segments
// compose: m_out = rho^L * m_in + C_seg.
// Phase 1 (proven shape: float2/thread, UNR=4, G=16, 4096 blocks, 40 regs,
//   ~6.9 TB/s = practical ceiling): per-segment coefficient C. Segment 0
//   seeds with m0=|init|; segment G-1 stores x[S-1].
// Phase 2 (tiny): combine G coefficients, reconstruct from x[S-1].
// PDL: phase1 launches dependents after its scan loop; phase2 front-loads
//   its phase1-independent prologue (rho/theta loads, sigmoid, rho^L) before
//   griddepcontrol.wait, so only the L2-hot g_C reads are exposed.

#define G   16
#define UNR 4
#define MAX_BF (32 * 4096)

__device__ float  g_C[G * MAX_BF];
__device__ float2 g_lx[MAX_BF];   // x at s = S-1 per chain

__device__ __forceinline__ float sigmoidf_(float x) {
    return 1.0f / (1.0f + expf(-x));
}

// |v| via single MUFU.RSQ
__device__ __forceinline__ float mag_(float vr, float vi) {
    float v2 = fmaxf(fmaf(vr, vr, vi * vi), 1e-37f);
    return v2 * rsqrtf(v2);
}

// x^e, integer e >= 0, by squaring (no MUFU)
__device__ __forceinline__ float powi_(float x, int e) {
    float r = 1.0f;
    while (e) {
        if (e & 1) r *= x;
        x *= x;
        e >>= 1;
    }
    return r;
}

__device__ __forceinline__ void pdl_trigger_() {
    asm volatile("griddepcontrol.launch_dependents;" ::: "memory");
}
__device__ __forceinline__ void pdl_wait_() {
    asm volatile("griddepcontrol.wait;" ::: "memory");
}

// ---------------- Phase 1: per-segment affine coefficient C ----------------
__global__ __launch_bounds__(256)
void phase1_kernel(const float* __restrict__ fr, const float* __restrict__ fi,
                   const float* __restrict__ ir, const float* __restrict__ ii,
                   const float* __restrict__ rho_logit,
                   int S, int F, int L)
{
    int F2 = F >> 1;
    int f2 = blockIdx.x * blockDim.x + threadIdx.x;
    if (f2 >= F2) return;
    int b = blockIdx.y;
    int g = blockIdx.z;

    float2 rl  = __ldg((const float2*)rho_logit + f2);
    float rho0 = sigmoidf_(rl.x), rho1 = sigmoidf_(rl.y);
    float om0  = 1.0f - rho0,     om1  = 1.0f - rho1;

    // Segment 0 seeds with m0=|init| -> its C becomes rho^L*m0 + C0.
    float C0 = 0.0f, C1 = 0.0f;
    if (g == 0) {
        size_t bfh = (size_t)b * (size_t)F2 + (size_t)f2;
        float2 s0 = __ldg((const float2*)ir + bfh);
        float2 s1 = __ldg((const float2*)ii + bfh);
        C0 = mag_(s0.x, s1.x);
        C1 = mag_(s0.y, s1.y);
    }

    size_t base = ((size_t)b * (size_t)S + (size_t)g * (size_t)L) * (size_t)F
                + (size_t)(f2 << 1);
    const float2* pr  = (const float2*)(fr + base);
    const float2* pim = (const float2*)(fi + base);
    size_t st = (size_t)F2;              // float2 stride per step

    float2 lxr = make_float2(0.f, 0.f), lxi = make_float2(0.f, 0.f);

    int nch = L / UNR;
    float2 cr[UNR], ci[UNR];
#pragma unroll
    for (int k = 0; k < UNR; ++k) {
        cr[k] = __ldcs(pr  + (size_t)k * st);
        ci[k] = __ldcs(pim + (size_t)k * st);
    }
    pr  += (size_t)UNR * st;
    pim += (size_t)UNR * st;

#pragma unroll 1
    for (int j = 0; j < nch; ++j) {
        float2 nr[UNR], ni[UNR];
        if (j + 1 < nch) {
#pragma unroll
            for (int k = 0; k < UNR; ++k) {
                nr[k] = __ldcs(pr  + (size_t)k * st);
                ni[k] = __ldcs(pim + (size_t)k * st);
            }
            pr  += (size_t)UNR * st;
            pim += (size_t)UNR * st;
        }
#pragma unroll
        for (int k = 0; k < UNR; ++k) {
            float wa = mag_(cr[k].x, ci[k].x);
            float wb = mag_(cr[k].y, ci[k].y);
            C0 = fmaf(rho0, C0, om0 * wa);
            C1 = fmaf(rho1, C1, om1 * wb);
            lxr = cr[k]; lxi = ci[k];
        }
#pragma unroll
        for (int k = 0; k < UNR; ++k) { cr[k] = nr[k]; ci[k] = ni[k]; }
    }

    // scan done -- let phase2 launch and run its prologue while we store
    pdl_trigger_();

    size_t bf0 = (size_t)b * (size_t)F + (size_t)(f2 << 1);
    *(float2*)(g_C + (size_t)g * MAX_BF + bf0) = make_float2(C0, C1);
    if (g == G - 1) {
        g_lx[bf0]     = make_float2(lxr.x, lxi.x);
        g_lx[bf0 + 1] = make_float2(lxr.y, lxi.y);
    }
}

// ---------------- Phase 2: combine segments, write output ----------------
__global__ __launch_bounds__(256)
void phase2_kernel(const float* __restrict__ fr, const float* __restrict__ fi,
                   const float* __restrict__ ir, const float* __restrict__ ii,
                   const float* __restrict__ rho_logit,
                   const float* __restrict__ theta_raw,
                   float2* __restrict__ out, int S, int F, int L)
{
    int f = blockIdx.x * blockDim.x + threadIdx.x;
    if (f >= F) { pdl_wait_(); return; }
    int b = blockIdx.y;
    size_t bf = (size_t)b * (size_t)F + (size_t)f;

    // ---- prologue: independent of phase1 (overlaps with phase1 tail) ----
    float thw = __ldg(theta_raw + f);
    float rho = sigmoidf_(__ldg(rho_logit + f));
    float D   = powi_(rho, L);   // 5 FMULs for L=32

    // ---- wait for phase1's grid (memory visible afterwards) ----
    pdl_wait_();

    if (thw == 0.0f) {
        // 16 independent loads, L2-hot (phase1 just wrote them)
        float c[G];
#pragma unroll
        for (int g = 0; g < G; ++g)
            c[g] = __ldg(g_C + (size_t)g * MAX_BF + bf);
        float2 lx = g_lx[bf];

        float m = c[0];            // init already folded into segment 0
#pragma unroll
        for (int g = 1; g < G; ++g)
            m = fmaf(D, m, c[g]);
        // m == z_last (real, >= 0).  out = x_last * m / |x_last|
        float w2 = fmaxf(fmaf(lx.x, lx.x, lx.y * lx.y), 1e-37f);
        float s  = m * rsqrtf(w2);
        out[bf] = make_float2(lx.x * s, lx.y * s);
    } else {
        // general complex-a path (not taken for this dataset): full rescan
        float th = 3.14159265358979323846f * tanhf(thw);
        float ss, sc;
        sincosf(th, &ss, &sc);
        float ar = rho * sc, ai = rho * ss, omr = 1.0f - rho;
        float m = mag_(__ldg(ir + bf), __ldg(ii + bf));
        const float* p  = fr + (size_t)b * (size_t)S * (size_t)F + f;
        const float* pi = fi + (size_t)b * (size_t)S * (size_t)F + f;
        float zr = 0.f, zi = 0.f, rinv = 1.f, lr = 0.f, li = 0.f;
        for (int s = 0; s < S; ++s) {
            float xr = __ldg(p), xi = __ldg(pi);
            p += F; pi += F;
            float x2 = fmaxf(fmaf(xr, xr, xi * xi), 1e-37f);
            float rv = rsqrtf(x2);
            float w  = x2 * rv;
            zr = fmaf(ar, m, omr * w);
            zi = ai * m;
            m = mag_(zr, zi);
            rinv = rv; lr = xr; li = xi;
        }
        out[bf] = make_float2((zr * lr - zi * li) * rinv,
                              fmaf(zr, li, zi * lr) * rinv);
    }
}

// ---------------- Monolithic fallback (unexpected shapes) ----------------
__global__ __launch_bounds__(256)
void mono_kernel(const float* __restrict__ fr, const float* __restrict__ fi,
                 const float* __restrict__ ir, const float* __restrict__ ii,
                 const float* __restrict__ rho_logit,
                 const float* __restrict__ theta_raw,
                 float2* __restrict__ out, int S, int F)
{
    int f = blockIdx.x * blockDim.x + threadIdx.x;
    if (f >= F) return;
    int b = blockIdx.y;
    size_t bf = (size_t)b * (size_t)F + (size_t)f;

    float rho = sigmoidf_(rho_logit[f]);
    float th  = 3.14159265358979323846f * tanhf(theta_raw[f]);
    float ss, sc;
    sincosf(th, &ss, &sc);
    float ar = rho * sc, ai = rho * ss, omr = 1.0f - rho;

    float m = mag_(ir[bf], ii[bf]);

    const float* pr  = fr + (size_t)b * (size_t)S * (size_t)F + f;
    const float* pim = fi + (size_t)b * (size_t)S * (size_t)F + f;
    float zr = 0.f, zi = 0.f, rinv = 1.f, lxr = 0.f, lxi = 0.f;
    for (int s = 0; s < S; ++s) {
        float xr = __ldcs(pr), xi = __ldcs(pim);
        pr += F; pim += F;
        float x2 = fmaxf(fmaf(xr, xr, xi * xi), 1e-37f);
        float rv = rsqrtf(x2);
        float w  = x2 * rv;
        zr = fmaf(ar, m, omr * w);
        zi = ai * m;
        m = mag_(zr, zi);
        rinv = rv; lxr = xr; lxi = xi;
    }
    out[bf] = make_float2((zr * lxr - zi * lxi) * rinv,
                          fmaf(zr, lxi, zi * lxr) * rinv);
}

extern "C" void kernel_launch(void* const* d_in, const int* in_sizes, int n_in,
                              void* d_out, int out_size)
{
    const float* fr = (const float*)d_in[0];
    const float* fi = (const float*)d_in[1];
    const float* ir = (const float*)d_in[2];
    const float* ii = (const float*)d_in[3];
    const float* rl = (const float*)d_in[4];
    const float* tr = (const float*)d_in[5];

    int F  = in_sizes[4];
    int BF = in_sizes[2];
    int B  = BF / F;
    int S  = in_sizes[0] / BF;

    dim3 block(256);

    bool fast = (BF <= MAX_BF) && (F % 512 == 0) && (S % (G * UNR) == 0);
    if (fast) {
        int L  = S / G;
        int F2 = F / 2;
        dim3 grid1(F2 / 256, B, G);
        phase1_kernel<<<grid1, block>>>(fr, fi, ir, ii, rl, S, F, L);

        // phase2 with Programmatic Stream Serialization (PDL overlap)
        cudaLaunchConfig_t cfg = {};
        cfg.gridDim  = dim3((F + 255) / 256, B, 1);
        cfg.blockDim = block;
        cfg.dynamicSmemBytes = 0;
        cfg.stream = 0;
        cudaLaunchAttribute attr[1];
        attr[0].id = cudaLaunchAttributeProgrammaticStreamSerialization;
        attr[0].val.programmaticStreamSerializationAllowed = 1;
        cfg.attrs = attr;
        cfg.numAttrs = 1;
        cudaLaunchKernelEx(&cfg, phase2_kernel, fr, fi, ir, ii, rl, tr,
                           (float2*)d_out, S, F, L);
    } else {
        dim3 grid((F + 255) / 256, B);
        mono_kernel<<<grid, block>>>(fr, fi, ir, ii, rl, tr,
                                     (float2*)d_out, S, F);
    }
}